// round 5
// baseline (speedup 1.0000x reference)
#include <cuda_runtime.h>
#include <cstdint>
#include <math.h>

// ---------------- problem constants ----------------
#define BB   4096
#define DD   256
#define HH   512
#define KK   10
#define HEADN 94
#define LL   4
#define SS   10
#define NOUT (DD * 30)          // 7680 pruned output cols

typedef unsigned long long ull;

// ---------------- scratch ----------------
__device__ float g_A0[BB * 2 * DD];          // concat(x*mask, mask)
__device__ float g_H[BB * HH];               // running hidden state
__device__ float g_Hr[BB * HH];              // relu(h)
__device__ float g_T[BB * HH];               // temp
__device__ float g_Tr[BB * HH];              // relu(temp)
__device__ float g_WFP[HH * NOUT];           // gathered W_fin
__device__ float g_BFP[NOUT];                // gathered b_fin
__device__ float g_OUT30[(size_t)BB * NOUT]; // final params

// ---------------- f32x2 helpers ----------------
__device__ __forceinline__ ull pack2(float lo, float hi) {
    ull r; asm("mov.b64 %0, {%1, %2};" : "=l"(r) : "f"(lo), "f"(hi)); return r;
}
__device__ __forceinline__ ull fma2(ull a, ull b, ull c) {
    ull r; asm("fma.rn.f32x2 %0, %1, %2, %3;" : "=l"(r) : "l"(a), "l"(b), "l"(c)); return r;
}
__device__ __forceinline__ void unpack2(ull v, float& lo, float& hi) {
    asm("mov.b64 {%0, %1}, %2;" : "=f"(lo), "=f"(hi) : "l"(v));
}

// ---------------- cp.async ----------------
__device__ __forceinline__ void cp_async16(uint32_t dst, const void* src) {
    asm volatile("cp.async.cg.shared.global [%0], [%1], 16;" :: "r"(dst), "l"(src));
}
__device__ __forceinline__ void cp_commit() { asm volatile("cp.async.commit_group;"); }
__device__ __forceinline__ void cp_wait0()  { asm volatile("cp.async.wait_group 0;"); }

// ---------------- threefry2x32 (bit-exact JAX) ----------------
__host__ __device__ __forceinline__ uint32_t rotl32(uint32_t x, int r) {
#if defined(__CUDA_ARCH__)
    return __funnelshift_l(x, x, r);
#else
    return (x << r) | (x >> (32 - r));
#endif
}

__host__ __device__ __forceinline__ void threefry2x32(
    uint32_t k0, uint32_t k1, uint32_t x0, uint32_t x1,
    uint32_t& o0, uint32_t& o1)
{
    uint32_t k2 = k0 ^ k1 ^ 0x1BD11BDAu;
    x0 += k0; x1 += k1;
    x0 += x1; x1 = rotl32(x1, 13); x1 ^= x0;
    x0 += x1; x1 = rotl32(x1, 15); x1 ^= x0;
    x0 += x1; x1 = rotl32(x1, 26); x1 ^= x0;
    x0 += x1; x1 = rotl32(x1, 6);  x1 ^= x0;
    x0 += k1; x1 += k2 + 1u;
    x0 += x1; x1 = rotl32(x1, 17); x1 ^= x0;
    x0 += x1; x1 = rotl32(x1, 29); x1 ^= x0;
    x0 += x1; x1 = rotl32(x1, 16); x1 ^= x0;
    x0 += x1; x1 = rotl32(x1, 24); x1 ^= x0;
    x0 += k2; x1 += k0 + 2u;
    x0 += x1; x1 = rotl32(x1, 13); x1 ^= x0;
    x0 += x1; x1 = rotl32(x1, 15); x1 ^= x0;
    x0 += x1; x1 = rotl32(x1, 26); x1 ^= x0;
    x0 += x1; x1 = rotl32(x1, 6);  x1 ^= x0;
    x0 += k0; x1 += k1 + 3u;
    x0 += x1; x1 = rotl32(x1, 17); x1 ^= x0;
    x0 += x1; x1 = rotl32(x1, 29); x1 ^= x0;
    x0 += x1; x1 = rotl32(x1, 16); x1 ^= x0;
    x0 += x1; x1 = rotl32(x1, 24); x1 ^= x0;
    x0 += k1; x1 += k2 + 4u;
    x0 += x1; x1 = rotl32(x1, 13); x1 ^= x0;
    x0 += x1; x1 = rotl32(x1, 15); x1 ^= x0;
    x0 += x1; x1 = rotl32(x1, 26); x1 ^= x0;
    x0 += x1; x1 = rotl32(x1, 6);  x1 ^= x0;
    x0 += k2; x1 += k0 + 5u;
    o0 = x0; o1 = x1;
}

__device__ __forceinline__ uint32_t tf_bits(uint32_t k0, uint32_t k1, uint32_t idx) {
    uint32_t o0, o1;
    threefry2x32(k0, k1, 0u, idx, o0, o1);
    return o0 ^ o1;
}

// ---------------- XLA-exact erfinv ----------------
__device__ __forceinline__ float erfinv_xla(float x) {
    float w = -logf((1.0f - x) * (1.0f + x));
    float p;
    if (w < 5.0f) {
        w -= 2.5f;
        p = 2.81022636e-08f;
        p = fmaf(p, w, 3.43273939e-07f);
        p = fmaf(p, w, -3.5233877e-06f);
        p = fmaf(p, w, -4.39150654e-06f);
        p = fmaf(p, w, 0.00021858087f);
        p = fmaf(p, w, -0.00125372503f);
        p = fmaf(p, w, -0.00417768164f);
        p = fmaf(p, w, 0.246640727f);
        p = fmaf(p, w, 1.50140941f);
    } else {
        w = sqrtf(w) - 3.0f;
        p = -0.000200214257f;
        p = fmaf(p, w, 0.000100950558f);
        p = fmaf(p, w, 0.00134934322f);
        p = fmaf(p, w, -0.00367342844f);
        p = fmaf(p, w, 0.00573950773f);
        p = fmaf(p, w, -0.0076224613f);
        p = fmaf(p, w, 0.00943887047f);
        p = fmaf(p, w, 1.00167406f);
        p = fmaf(p, w, 2.83297682f);
    }
    return p * x;
}

__device__ __forceinline__ float bits_to_unit(uint32_t b) {
    return __uint_as_float((b >> 9) | 0x3F800000u) - 1.0f;
}

__device__ __forceinline__ float gumbel_from_bits(uint32_t bits) {
    const float TINY = 1.17549435e-38f;
    float f = bits_to_unit(bits);
    float u = fmaxf(TINY, f + TINY);
    return -logf(-logf(u));
}

// ---------------- prep / gather ----------------
__global__ void prep_kernel(const float* __restrict__ x, const float* __restrict__ mask) {
    int t = blockIdx.x * blockDim.x + threadIdx.x;
    if (t >= BB * 2 * DD) return;
    int b = t >> 9;
    int c = t & 511;
    float v;
    if (c < DD) v = x[b * DD + c] * mask[b * DD + c];
    else        v = mask[b * DD + (c - DD)];
    g_A0[t] = v;
}

__global__ void gather_kernel(const float* __restrict__ Wf, const float* __restrict__ bf) {
    int t = blockIdx.x * blockDim.x + threadIdx.x;
    const int total = HH * NOUT;
    if (t < total) {
        int c = t % NOUT;
        int h = t / NOUT;
        int d = c / 30, j = c - d * 30;
        g_WFP[t] = Wf[(size_t)h * (DD * HEADN) + d * HEADN + j];
    } else if (t < total + NOUT) {
        int c = t - total;
        int d = c / 30, j = c - d * 30;
        g_BFP[c] = bf[d * HEADN + j];
    }
}

// ---------------- SGEMM: TM x 128 tile, BK=32, 128 threads, cp.async B ----------------
// A plain fp32 [M,K] row-major, C = A @ B + bias (+C). Optionally writes relu(C) to R.
template <int TM, bool ADD_C, bool WRITE_RELU>
__global__ __launch_bounds__(128, (TM == 64) ? 4 : 5) void sgemm2(
    const float* __restrict__ A, const float* __restrict__ Bm,
    const float* __restrict__ bias, float* __restrict__ C,
    float* __restrict__ R, int N, int Kd)
{
    constexpr int AST = TM + 4;                 // padded As row stride
    constexpr int RPT = TM / 8;                 // rows per thread (8 or 4)
    constexpr int TPR = 128 / TM;               // threads per A row (2 or 4)
    constexpr int ASPAN = 32 / TPR;             // k floats per thread (16 or 8)

    extern __shared__ float sm[];
    float* As = sm;                              // [2][32][AST]
    float* Bs = sm + 2 * 32 * AST;               // [2][32][128]

    const int t  = threadIdx.x;
    const int bm = blockIdx.y * TM;
    const int bn = blockIdx.x * 128;
    const int tx = t & 15;
    const int ty = t >> 4;                       // 0..7
    const int rowbase = ty * RPT;

    const int arow = t / TPR;                    // 0..TM-1
    const int akq  = (t % TPR) * ASPAN;
    const float* Ap = A + (size_t)(bm + arow) * Kd + akq;

    const int brow = t >> 5;                     // 0..3
    const int bcol = (t & 31) * 4;
    const float* Bp = Bm + bn + bcol;
    const uint32_t bs_base = (uint32_t)__cvta_generic_to_shared(Bs);

    ull acc2[RPT][4];
#pragma unroll
    for (int i = 0; i < RPT; i++)
#pragma unroll
        for (int j = 0; j < 4; j++) acc2[i][j] = 0ull;

    float4 aR[ASPAN / 4];

    auto issueB = [&](int k0, int p) {
#pragma unroll
        for (int i = 0; i < 8; i++) {
            int r = brow + 4 * i;
            uint32_t dst = bs_base + ((p * 32 + r) * 128 + bcol) * 4;
            cp_async16(dst, Bp + (size_t)(k0 + r) * N);
        }
    };
    auto loadA = [&](int k0) {
#pragma unroll
        for (int j = 0; j < ASPAN / 4; j++)
            aR[j] = *reinterpret_cast<const float4*>(Ap + k0 + 4 * j);
    };
    auto storeA = [&](int p) {
        float* dst = As + p * 32 * AST;
#pragma unroll
        for (int j = 0; j < ASPAN / 4; j++) {
            dst[(akq + 4 * j + 0) * AST + arow] = aR[j].x;
            dst[(akq + 4 * j + 1) * AST + arow] = aR[j].y;
            dst[(akq + 4 * j + 2) * AST + arow] = aR[j].z;
            dst[(akq + 4 * j + 3) * AST + arow] = aR[j].w;
        }
    };

    issueB(0, 0);
    cp_commit();
    loadA(0);
    storeA(0);
    cp_wait0();
    __syncthreads();

    const int T = Kd >> 5;
    int p = 0;
#pragma unroll 1
    for (int tk = 0; tk < T; tk++) {
        if (tk + 1 < T) {
            issueB((tk + 1) << 5, p ^ 1);
            cp_commit();
            loadA((tk + 1) << 5);
        }
        const float* Asp = As + p * 32 * AST;
        const float* Bsp = Bs + p * 32 * 128;
#pragma unroll
        for (int kk = 0; kk < 32; kk++) {
            float a[RPT];
#pragma unroll
            for (int j = 0; j < RPT / 4; j++)
                *reinterpret_cast<float4*>(a + 4 * j) =
                    *reinterpret_cast<const float4*>(&Asp[kk * AST + rowbase + 4 * j]);
            ulonglong2 bq0 = *reinterpret_cast<const ulonglong2*>(&Bsp[kk * 128 + tx * 8]);
            ulonglong2 bq1 = *reinterpret_cast<const ulonglong2*>(&Bsp[kk * 128 + tx * 8 + 4]);
#pragma unroll
            for (int i = 0; i < RPT; i++) {
                ull a2 = pack2(a[i], a[i]);
                acc2[i][0] = fma2(a2, bq0.x, acc2[i][0]);
                acc2[i][1] = fma2(a2, bq0.y, acc2[i][1]);
                acc2[i][2] = fma2(a2, bq1.x, acc2[i][2]);
                acc2[i][3] = fma2(a2, bq1.y, acc2[i][3]);
            }
        }
        if (tk + 1 < T) {
            storeA(p ^ 1);
            cp_wait0();
            __syncthreads();
            p ^= 1;
        }
    }

    // epilogue
    float4 bia0 = *reinterpret_cast<const float4*>(bias + bn + tx * 8);
    float4 bia1 = *reinterpret_cast<const float4*>(bias + bn + tx * 8 + 4);
#pragma unroll
    for (int i = 0; i < RPT; i++) {
        size_t roff = (size_t)(bm + rowbase + i) * N + bn + tx * 8;
        float v[8];
        unpack2(acc2[i][0], v[0], v[1]);
        unpack2(acc2[i][1], v[2], v[3]);
        unpack2(acc2[i][2], v[4], v[5]);
        unpack2(acc2[i][3], v[6], v[7]);
        float4 r0, r1;
        r0.x = v[0] + bia0.x; r0.y = v[1] + bia0.y;
        r0.z = v[2] + bia0.z; r0.w = v[3] + bia0.w;
        r1.x = v[4] + bia1.x; r1.y = v[5] + bia1.y;
        r1.z = v[6] + bia1.z; r1.w = v[7] + bia1.w;
        if (ADD_C) {
            float4 c0 = *reinterpret_cast<const float4*>(C + roff);
            float4 c1 = *reinterpret_cast<const float4*>(C + roff + 4);
            r0.x += c0.x; r0.y += c0.y; r0.z += c0.z; r0.w += c0.w;
            r1.x += c1.x; r1.y += c1.y; r1.z += c1.z; r1.w += c1.w;
        }
        *reinterpret_cast<float4*>(C + roff)     = r0;
        *reinterpret_cast<float4*>(C + roff + 4) = r1;
        if (WRITE_RELU) {
            float4 q0, q1;
            q0.x = fmaxf(r0.x, 0.f); q0.y = fmaxf(r0.y, 0.f);
            q0.z = fmaxf(r0.z, 0.f); q0.w = fmaxf(r0.w, 0.f);
            q1.x = fmaxf(r1.x, 0.f); q1.y = fmaxf(r1.y, 0.f);
            q1.z = fmaxf(r1.z, 0.f); q1.w = fmaxf(r1.w, 0.f);
            *reinterpret_cast<float4*>(R + roff)     = q0;
            *reinterpret_cast<float4*>(R + roff + 4) = q1;
        }
    }
}

// ---------------- fused tail ----------------
__global__ void fused_tail(const float* __restrict__ x, const float* __restrict__ mask,
                           float* __restrict__ out,
                           uint32_t kc0, uint32_t kc1, uint32_t kn0, uint32_t kn1)
{
    int t = blockIdx.x * blockDim.x + threadIdx.x;
    if (t >= BB * DD) return;
    int b = t >> 8;
    int d = t & (DD - 1);

    const float* row = g_OUT30 + (size_t)b * NOUT + d * 30;
    float lg[KK], mu[KK], sc[KK];
#pragma unroll
    for (int j = 0; j < KK; j++) lg[j] = row[j];
#pragma unroll
    for (int j = 0; j < KK; j++) mu[j] = row[KK + j];
#pragma unroll
    for (int j = 0; j < KK; j++) {
        float v = row[2 * KK + j];
        sc[j] = fmaxf(v, 0.0f) + log1pf(expf(-fabsf(v))) + 0.001f;
    }
    float q  = 1.0f - mask[t];
    float xu = x[t] * q;

    float mx = lg[0];
#pragma unroll
    for (int j = 1; j < KK; j++) mx = fmaxf(mx, lg[j]);
    float se = 0.0f;
#pragma unroll
    for (int j = 0; j < KK; j++) se += expf(lg[j] - mx);
    float lse = logf(se);

    float term[KK];
    float m2 = -1e30f;
#pragma unroll
    for (int j = 0; j < KK; j++) {
        float z   = (xu - mu[j]) / sc[j];
        float cll = -0.5f * z * z - logf(sc[j]) - 0.9189385332046727f;
        term[j] = (lg[j] - mx - lse) + cll;
        m2 = fmaxf(m2, term[j]);
    }
    float s2 = 0.0f;
#pragma unroll
    for (int j = 0; j < KK; j++) s2 += expf(term[j] - m2);
    out[t] = (m2 + logf(s2)) * q;

    float pm = 0.0f;
#pragma unroll
    for (int j = 0; j < KK; j++) pm += (expf(lg[j] - mx) / se) * mu[j];
    out[BB * DD + SS * BB * DD + t] = pm * q;

    float* smp = out + BB * DD;

#pragma unroll 1
    for (int s = 0; s < SS; s++) {
        uint32_t idx_e = (uint32_t)(s * BB + b) * DD + (uint32_t)d;
        uint32_t base  = idx_e * KK;
        float best = -1e30f;
        int a = 0;
#pragma unroll
        for (int j = 0; j < KK; j++) {
            uint32_t bits = tf_bits(kc0, kc1, base + j);
            float v = lg[j] + gumbel_from_bits(bits);
            if (v > best) { best = v; a = j; }
        }
        float mua = 0.f, sca = 0.f;
#pragma unroll
        for (int j = 0; j < KK; j++) {
            if (a == j) { mua = mu[j]; sca = sc[j]; }
        }
        uint32_t ebits = tf_bits(kn0, kn1, idx_e);
        const float LO = -0.99999994f;
        float u = fmaxf(LO, fmaf(bits_to_unit(ebits), 2.0f, LO));
        float eps = 1.41421356237309515f * erfinv_xla(u);
        smp[(b * SS + s) * DD + d] = (mua + sca * eps) * q;
    }
}

// ---------------- launch ----------------
extern "C" void kernel_launch(void* const* d_in, const int* in_sizes, int n_in,
                              void* d_out, int out_size)
{
    const float* x     = (const float*)d_in[0];
    const float* mask  = (const float*)d_in[1];
    const float* W_in  = (const float*)d_in[2];
    const float* b_in  = (const float*)d_in[3];
    const float* W1    = (const float*)d_in[4];
    const float* b1    = (const float*)d_in[5];
    const float* W2    = (const float*)d_in[6];
    const float* b2    = (const float*)d_in[7];
    const float* W_fin = (const float*)d_in[8];
    const float* b_fin = (const float*)d_in[9];
    float* out = (float*)d_out;

    float *dA0, *dH, *dHr, *dT, *dTr, *dWFP, *dBFP, *dOUT30;
    cudaGetSymbolAddress((void**)&dA0,    g_A0);
    cudaGetSymbolAddress((void**)&dH,     g_H);
    cudaGetSymbolAddress((void**)&dHr,    g_Hr);
    cudaGetSymbolAddress((void**)&dT,     g_T);
    cudaGetSymbolAddress((void**)&dTr,    g_Tr);
    cudaGetSymbolAddress((void**)&dWFP,   g_WFP);
    cudaGetSymbolAddress((void**)&dBFP,   g_BFP);
    cudaGetSymbolAddress((void**)&dOUT30, g_OUT30);

    uint32_t kc0, kc1, kn0, kn1;
    threefry2x32(0u, 1234u, 0u, 0u, kc0, kc1);   // keys[0] -> categorical
    threefry2x32(0u, 1234u, 0u, 1u, kn0, kn1);   // keys[1] -> normal

    const int SMEM32 = (2 * 32 * 36 + 2 * 32 * 128) * 4;   // 41984
    const int SMEM64 = (2 * 32 * 68 + 2 * 32 * 128) * 4;   // 50176
    cudaFuncSetAttribute(sgemm2<32, false, true>,
                         cudaFuncAttributeMaxDynamicSharedMemorySize, SMEM32);
    cudaFuncSetAttribute(sgemm2<32, true, true>,
                         cudaFuncAttributeMaxDynamicSharedMemorySize, SMEM32);
    cudaFuncSetAttribute(sgemm2<64, false, false>,
                         cudaFuncAttributeMaxDynamicSharedMemorySize, SMEM64);

    prep_kernel<<<(BB * 2 * DD + 255) / 256, 256>>>(x, mask);
    gather_kernel<<<(HH * NOUT + NOUT + 255) / 256, 256>>>(W_fin, b_fin);

    dim3 blk(128);
    dim3 g1(HH / 128, BB / 32);                  // 4 x 128 = 512 CTAs
    // h = A0 @ W_in + b_in ; also relu(h)
    sgemm2<32, false, true><<<g1, blk, SMEM32>>>(dA0, W_in, b_in, dH, dHr, HH, 2 * DD);
    for (int l = 0; l < LL; l++) {
        // t = relu(h) @ W1 + b1 ; also relu(t)
        sgemm2<32, false, true><<<g1, blk, SMEM32>>>(dHr, W1 + (size_t)l * HH * HH, b1 + l * HH, dT, dTr, HH, HH);
        // h = h + relu(t) @ W2 + b2 ; also relu(h)
        sgemm2<32, true, true><<<g1, blk, SMEM32>>>(dTr, W2 + (size_t)l * HH * HH, b2 + l * HH, dH, dHr, HH, HH);
    }
    // final pruned GEMM
    dim3 g2(NOUT / 128, BB / 64);                // 60 x 64 = 3840 CTAs
    sgemm2<64, false, false><<<g2, blk, SMEM64>>>(dH, dWFP, dBFP, dOUT30, nullptr, NOUT, HH);

    fused_tail<<<(BB * DD + 255) / 256, 256>>>(x, mask, out, kc0, kc1, kn0, kn1);
}

// round 6
// speedup vs baseline: 1.0340x; 1.0340x over previous
#include <cuda_runtime.h>
#include <cstdint>
#include <math.h>

// ---------------- problem constants ----------------
#define BB   4096
#define DD   256
#define HH   512
#define KK   10
#define HEADN 94
#define LL   4
#define SS   10
#define NOUT (DD * 30)          // 7680 pruned output cols

typedef unsigned long long ull;

// ---------------- scratch ----------------
__device__ float g_A0[BB * 2 * DD];          // concat(x*mask, mask)
__device__ float g_H[BB * HH];               // running hidden state
__device__ float g_Hr[BB * HH];              // relu(h)
__device__ float g_T[BB * HH];               // temp
__device__ float g_Tr[BB * HH];              // relu(temp)
__device__ float g_WFP[HH * NOUT];           // gathered W_fin
__device__ float g_BFP[NOUT];                // gathered b_fin
__device__ float g_OUT30[(size_t)BB * NOUT]; // final params

// ---------------- f32x2 helpers ----------------
__device__ __forceinline__ ull fma2(ull a, ull b, ull c) {
    ull r; asm("fma.rn.f32x2 %0, %1, %2, %3;" : "=l"(r) : "l"(a), "l"(b), "l"(c)); return r;
}
__device__ __forceinline__ void unpack2(ull v, float& lo, float& hi) {
    asm("mov.b64 {%0, %1}, %2;" : "=f"(lo), "=f"(hi) : "l"(v));
}

// ---------------- cp.async ----------------
__device__ __forceinline__ void cp_async16(uint32_t dst, const void* src) {
    asm volatile("cp.async.cg.shared.global [%0], [%1], 16;" :: "r"(dst), "l"(src));
}
__device__ __forceinline__ void cp_commit() { asm volatile("cp.async.commit_group;"); }
__device__ __forceinline__ void cp_wait0()  { asm volatile("cp.async.wait_group 0;"); }

// ---------------- threefry2x32 (bit-exact JAX) ----------------
__host__ __device__ __forceinline__ uint32_t rotl32(uint32_t x, int r) {
#if defined(__CUDA_ARCH__)
    return __funnelshift_l(x, x, r);
#else
    return (x << r) | (x >> (32 - r));
#endif
}

__host__ __device__ __forceinline__ void threefry2x32(
    uint32_t k0, uint32_t k1, uint32_t x0, uint32_t x1,
    uint32_t& o0, uint32_t& o1)
{
    uint32_t k2 = k0 ^ k1 ^ 0x1BD11BDAu;
    x0 += k0; x1 += k1;
    x0 += x1; x1 = rotl32(x1, 13); x1 ^= x0;
    x0 += x1; x1 = rotl32(x1, 15); x1 ^= x0;
    x0 += x1; x1 = rotl32(x1, 26); x1 ^= x0;
    x0 += x1; x1 = rotl32(x1, 6);  x1 ^= x0;
    x0 += k1; x1 += k2 + 1u;
    x0 += x1; x1 = rotl32(x1, 17); x1 ^= x0;
    x0 += x1; x1 = rotl32(x1, 29); x1 ^= x0;
    x0 += x1; x1 = rotl32(x1, 16); x1 ^= x0;
    x0 += x1; x1 = rotl32(x1, 24); x1 ^= x0;
    x0 += k2; x1 += k0 + 2u;
    x0 += x1; x1 = rotl32(x1, 13); x1 ^= x0;
    x0 += x1; x1 = rotl32(x1, 15); x1 ^= x0;
    x0 += x1; x1 = rotl32(x1, 26); x1 ^= x0;
    x0 += x1; x1 = rotl32(x1, 6);  x1 ^= x0;
    x0 += k0; x1 += k1 + 3u;
    x0 += x1; x1 = rotl32(x1, 17); x1 ^= x0;
    x0 += x1; x1 = rotl32(x1, 29); x1 ^= x0;
    x0 += x1; x1 = rotl32(x1, 16); x1 ^= x0;
    x0 += x1; x1 = rotl32(x1, 24); x1 ^= x0;
    x0 += k1; x1 += k2 + 4u;
    x0 += x1; x1 = rotl32(x1, 13); x1 ^= x0;
    x0 += x1; x1 = rotl32(x1, 15); x1 ^= x0;
    x0 += x1; x1 = rotl32(x1, 26); x1 ^= x0;
    x0 += x1; x1 = rotl32(x1, 6);  x1 ^= x0;
    x0 += k2; x1 += k0 + 5u;
    o0 = x0; o1 = x1;
}

__device__ __forceinline__ uint32_t tf_bits(uint32_t k0, uint32_t k1, uint32_t idx) {
    uint32_t o0, o1;
    threefry2x32(k0, k1, 0u, idx, o0, o1);
    return o0 ^ o1;
}

// ---------------- XLA-exact erfinv ----------------
__device__ __forceinline__ float erfinv_xla(float x) {
    float w = -logf((1.0f - x) * (1.0f + x));
    float p;
    if (w < 5.0f) {
        w -= 2.5f;
        p = 2.81022636e-08f;
        p = fmaf(p, w, 3.43273939e-07f);
        p = fmaf(p, w, -3.5233877e-06f);
        p = fmaf(p, w, -4.39150654e-06f);
        p = fmaf(p, w, 0.00021858087f);
        p = fmaf(p, w, -0.00125372503f);
        p = fmaf(p, w, -0.00417768164f);
        p = fmaf(p, w, 0.246640727f);
        p = fmaf(p, w, 1.50140941f);
    } else {
        w = sqrtf(w) - 3.0f;
        p = -0.000200214257f;
        p = fmaf(p, w, 0.000100950558f);
        p = fmaf(p, w, 0.00134934322f);
        p = fmaf(p, w, -0.00367342844f);
        p = fmaf(p, w, 0.00573950773f);
        p = fmaf(p, w, -0.0076224613f);
        p = fmaf(p, w, 0.00943887047f);
        p = fmaf(p, w, 1.00167406f);
        p = fmaf(p, w, 2.83297682f);
    }
    return p * x;
}

__device__ __forceinline__ float bits_to_unit(uint32_t b) {
    return __uint_as_float((b >> 9) | 0x3F800000u) - 1.0f;
}

__device__ __forceinline__ float gumbel_from_bits(uint32_t bits) {
    const float TINY = 1.17549435e-38f;
    float f = bits_to_unit(bits);
    float u = fmaxf(TINY, f + TINY);
    return -logf(-logf(u));
}

// ---------------- prep / gather ----------------
__global__ void prep_kernel(const float* __restrict__ x, const float* __restrict__ mask) {
    int t = blockIdx.x * blockDim.x + threadIdx.x;
    if (t >= BB * 2 * DD) return;
    int b = t >> 9;
    int c = t & 511;
    float v;
    if (c < DD) v = x[b * DD + c] * mask[b * DD + c];
    else        v = mask[b * DD + (c - DD)];
    g_A0[t] = v;
}

__global__ void gather_kernel(const float* __restrict__ Wf, const float* __restrict__ bf) {
    int t = blockIdx.x * blockDim.x + threadIdx.x;
    const int total = HH * NOUT;
    if (t < total) {
        int c = t % NOUT;
        int h = t / NOUT;
        int d = c / 30, j = c - d * 30;
        g_WFP[t] = Wf[(size_t)h * (DD * HEADN) + d * HEADN + j];
    } else if (t < total + NOUT) {
        int c = t - total;
        int d = c / 30, j = c - d * 30;
        g_BFP[c] = bf[d * HEADN + j];
    }
}

// ---------------- SGEMM: 64x128 tile, BK=32, 128 threads, dup-A smem ----------------
// C = A @ B + bias (+C). Optionally writes relu(C) to R. A has NO relu (producers
// pre-write relu'd copies).
template <bool ADD_C, bool WRITE_RELU>
__global__ __launch_bounds__(128, 3) void sgemm3(
    const float* __restrict__ A, const float* __restrict__ Bm,
    const float* __restrict__ bias, float* __restrict__ C,
    float* __restrict__ R, int N, int Kd)
{
    // As: duplicated-transposed A tile: As[buf][k][2*row+{0,1}] (stride 128 floats)
    // Bs: Bs[buf][k][col]
    extern __shared__ float sm[];
    float* As = sm;                      // 2 * 32 * 128
    float* Bs = sm + 2 * 32 * 128;       // 2 * 32 * 128

    const int t  = threadIdx.x;
    const int bm = blockIdx.y * 64;
    const int bn = blockIdx.x * 128;
    const int tx = t & 15;
    const int ty = t >> 4;               // 0..7
    const int rowbase = ty * 8;

    // A fill: row = t>>1 (0..63), 16 consecutive k at (t&1)*16
    const int arow = t >> 1;
    const int ak   = (t & 1) * 16;
    const float* Ap = A + (size_t)(bm + arow) * Kd + ak;

    // B fill: 8 cp.async16 per thread
    const int brow = t >> 5;              // 0..3
    const int bcol = (t & 31) * 4;
    const float* Bp = Bm + bn + bcol;
    const uint32_t bs_base = (uint32_t)__cvta_generic_to_shared(Bs);

    ull acc2[8][4];
#pragma unroll
    for (int i = 0; i < 8; i++)
#pragma unroll
        for (int j = 0; j < 4; j++) acc2[i][j] = 0ull;

    float4 aR[4];

    auto issueB = [&](int k0, int p) {
#pragma unroll
        for (int i = 0; i < 8; i++) {
            int r = brow + 4 * i;
            uint32_t dst = bs_base + (uint32_t)(((p * 32 + r) * 128 + bcol) * 4);
            cp_async16(dst, Bp + (size_t)(k0 + r) * N);
        }
    };
    auto loadA = [&](int k0) {
#pragma unroll
        for (int j = 0; j < 4; j++)
            aR[j] = *reinterpret_cast<const float4*>(Ap + k0 + 4 * j);
    };
    auto storeA = [&](int p) {
        float* dst = As + p * 32 * 128 + 2 * arow;
#pragma unroll
        for (int j = 0; j < 4; j++) {
            float v[4] = {aR[j].x, aR[j].y, aR[j].z, aR[j].w};
#pragma unroll
            for (int m = 0; m < 4; m++) {
                float2 dup = make_float2(v[m], v[m]);
                *reinterpret_cast<float2*>(dst + (ak + 4 * j + m) * 128) = dup;
            }
        }
    };

    issueB(0, 0);
    cp_commit();
    loadA(0);
    storeA(0);
    cp_wait0();
    __syncthreads();

    const int T = Kd >> 5;
    int p = 0;
#pragma unroll 1
    for (int tk = 0; tk < T; tk++) {
        if (tk + 1 < T) {
            issueB((tk + 1) << 5, p ^ 1);
            cp_commit();
            loadA((tk + 1) << 5);
        }
        const float* Asp = As + p * 32 * 128 + 2 * rowbase;
        const float* Bsp = Bs + p * 32 * 128 + tx * 8;
#pragma unroll
        for (int kk = 0; kk < 32; kk++) {
            ulonglong2 aq0 = *reinterpret_cast<const ulonglong2*>(Asp + kk * 128);
            ulonglong2 aq1 = *reinterpret_cast<const ulonglong2*>(Asp + kk * 128 + 4);
            ulonglong2 aq2 = *reinterpret_cast<const ulonglong2*>(Asp + kk * 128 + 8);
            ulonglong2 aq3 = *reinterpret_cast<const ulonglong2*>(Asp + kk * 128 + 12);
            ulonglong2 bq0 = *reinterpret_cast<const ulonglong2*>(Bsp + kk * 128);
            ulonglong2 bq1 = *reinterpret_cast<const ulonglong2*>(Bsp + kk * 128 + 4);
            acc2[0][0] = fma2(aq0.x, bq0.x, acc2[0][0]);
            acc2[0][1] = fma2(aq0.x, bq0.y, acc2[0][1]);
            acc2[0][2] = fma2(aq0.x, bq1.x, acc2[0][2]);
            acc2[0][3] = fma2(aq0.x, bq1.y, acc2[0][3]);
            acc2[1][0] = fma2(aq0.y, bq0.x, acc2[1][0]);
            acc2[1][1] = fma2(aq0.y, bq0.y, acc2[1][1]);
            acc2[1][2] = fma2(aq0.y, bq1.x, acc2[1][2]);
            acc2[1][3] = fma2(aq0.y, bq1.y, acc2[1][3]);
            acc2[2][0] = fma2(aq1.x, bq0.x, acc2[2][0]);
            acc2[2][1] = fma2(aq1.x, bq0.y, acc2[2][1]);
            acc2[2][2] = fma2(aq1.x, bq1.x, acc2[2][2]);
            acc2[2][3] = fma2(aq1.x, bq1.y, acc2[2][3]);
            acc2[3][0] = fma2(aq1.y, bq0.x, acc2[3][0]);
            acc2[3][1] = fma2(aq1.y, bq0.y, acc2[3][1]);
            acc2[3][2] = fma2(aq1.y, bq1.x, acc2[3][2]);
            acc2[3][3] = fma2(aq1.y, bq1.y, acc2[3][3]);
            acc2[4][0] = fma2(aq2.x, bq0.x, acc2[4][0]);
            acc2[4][1] = fma2(aq2.x, bq0.y, acc2[4][1]);
            acc2[4][2] = fma2(aq2.x, bq1.x, acc2[4][2]);
            acc2[4][3] = fma2(aq2.x, bq1.y, acc2[4][3]);
            acc2[5][0] = fma2(aq2.y, bq0.x, acc2[5][0]);
            acc2[5][1] = fma2(aq2.y, bq0.y, acc2[5][1]);
            acc2[5][2] = fma2(aq2.y, bq1.x, acc2[5][2]);
            acc2[5][3] = fma2(aq2.y, bq1.y, acc2[5][3]);
            acc2[6][0] = fma2(aq3.x, bq0.x, acc2[6][0]);
            acc2[6][1] = fma2(aq3.x, bq0.y, acc2[6][1]);
            acc2[6][2] = fma2(aq3.x, bq1.x, acc2[6][2]);
            acc2[6][3] = fma2(aq3.x, bq1.y, acc2[6][3]);
            acc2[7][0] = fma2(aq3.y, bq0.x, acc2[7][0]);
            acc2[7][1] = fma2(aq3.y, bq0.y, acc2[7][1]);
            acc2[7][2] = fma2(aq3.y, bq1.x, acc2[7][2]);
            acc2[7][3] = fma2(aq3.y, bq1.y, acc2[7][3]);
        }
        if (tk + 1 < T) {
            storeA(p ^ 1);
            cp_wait0();
            __syncthreads();
            p ^= 1;
        }
    }

    // epilogue
    float4 bia0 = *reinterpret_cast<const float4*>(bias + bn + tx * 8);
    float4 bia1 = *reinterpret_cast<const float4*>(bias + bn + tx * 8 + 4);
#pragma unroll
    for (int i = 0; i < 8; i++) {
        size_t roff = (size_t)(bm + rowbase + i) * N + bn + tx * 8;
        float v[8];
        unpack2(acc2[i][0], v[0], v[1]);
        unpack2(acc2[i][1], v[2], v[3]);
        unpack2(acc2[i][2], v[4], v[5]);
        unpack2(acc2[i][3], v[6], v[7]);
        float4 r0, r1;
        r0.x = v[0] + bia0.x; r0.y = v[1] + bia0.y;
        r0.z = v[2] + bia0.z; r0.w = v[3] + bia0.w;
        r1.x = v[4] + bia1.x; r1.y = v[5] + bia1.y;
        r1.z = v[6] + bia1.z; r1.w = v[7] + bia1.w;
        if (ADD_C) {
            float4 c0 = *reinterpret_cast<const float4*>(C + roff);
            float4 c1 = *reinterpret_cast<const float4*>(C + roff + 4);
            r0.x += c0.x; r0.y += c0.y; r0.z += c0.z; r0.w += c0.w;
            r1.x += c1.x; r1.y += c1.y; r1.z += c1.z; r1.w += c1.w;
        }
        *reinterpret_cast<float4*>(C + roff)     = r0;
        *reinterpret_cast<float4*>(C + roff + 4) = r1;
        if (WRITE_RELU) {
            float4 q0, q1;
            q0.x = fmaxf(r0.x, 0.f); q0.y = fmaxf(r0.y, 0.f);
            q0.z = fmaxf(r0.z, 0.f); q0.w = fmaxf(r0.w, 0.f);
            q1.x = fmaxf(r1.x, 0.f); q1.y = fmaxf(r1.y, 0.f);
            q1.z = fmaxf(r1.z, 0.f); q1.w = fmaxf(r1.w, 0.f);
            *reinterpret_cast<float4*>(R + roff)     = q0;
            *reinterpret_cast<float4*>(R + roff + 4) = q1;
        }
    }
}

// ---------------- fused tail ----------------
__global__ void fused_tail(const float* __restrict__ x, const float* __restrict__ mask,
                           float* __restrict__ out,
                           uint32_t kc0, uint32_t kc1, uint32_t kn0, uint32_t kn1)
{
    int t = blockIdx.x * blockDim.x + threadIdx.x;
    if (t >= BB * DD) return;
    int b = t >> 8;
    int d = t & (DD - 1);

    const float* row = g_OUT30 + (size_t)b * NOUT + d * 30;
    float lg[KK], mu[KK], sc[KK];
#pragma unroll
    for (int j = 0; j < KK; j++) lg[j] = row[j];
#pragma unroll
    for (int j = 0; j < KK; j++) mu[j] = row[KK + j];
#pragma unroll
    for (int j = 0; j < KK; j++) {
        float v = row[2 * KK + j];
        sc[j] = fmaxf(v, 0.0f) + log1pf(expf(-fabsf(v))) + 0.001f;
    }
    float q  = 1.0f - mask[t];
    float xu = x[t] * q;

    float mx = lg[0];
#pragma unroll
    for (int j = 1; j < KK; j++) mx = fmaxf(mx, lg[j]);
    float se = 0.0f;
#pragma unroll
    for (int j = 0; j < KK; j++) se += expf(lg[j] - mx);
    float lse = logf(se);

    float term[KK];
    float m2 = -1e30f;
#pragma unroll
    for (int j = 0; j < KK; j++) {
        float z   = (xu - mu[j]) / sc[j];
        float cll = -0.5f * z * z - logf(sc[j]) - 0.9189385332046727f;
        term[j] = (lg[j] - mx - lse) + cll;
        m2 = fmaxf(m2, term[j]);
    }
    float s2 = 0.0f;
#pragma unroll
    for (int j = 0; j < KK; j++) s2 += expf(term[j] - m2);
    out[t] = (m2 + logf(s2)) * q;

    float pm = 0.0f;
#pragma unroll
    for (int j = 0; j < KK; j++) pm += (expf(lg[j] - mx) / se) * mu[j];
    out[BB * DD + SS * BB * DD + t] = pm * q;

    float* smp = out + BB * DD;

#pragma unroll 1
    for (int s = 0; s < SS; s++) {
        uint32_t idx_e = (uint32_t)(s * BB + b) * DD + (uint32_t)d;
        uint32_t base  = idx_e * KK;
        float best = -1e30f;
        int a = 0;
#pragma unroll
        for (int j = 0; j < KK; j++) {
            uint32_t bits = tf_bits(kc0, kc1, base + j);
            float v = lg[j] + gumbel_from_bits(bits);
            if (v > best) { best = v; a = j; }
        }
        float mua = 0.f, sca = 0.f;
#pragma unroll
        for (int j = 0; j < KK; j++) {
            if (a == j) { mua = mu[j]; sca = sc[j]; }
        }
        uint32_t ebits = tf_bits(kn0, kn1, idx_e);
        const float LO = -0.99999994f;
        float u = fmaxf(LO, fmaf(bits_to_unit(ebits), 2.0f, LO));
        float eps = 1.41421356237309515f * erfinv_xla(u);
        smp[(b * SS + s) * DD + d] = (mua + sca * eps) * q;
    }
}

// ---------------- launch ----------------
extern "C" void kernel_launch(void* const* d_in, const int* in_sizes, int n_in,
                              void* d_out, int out_size)
{
    const float* x     = (const float*)d_in[0];
    const float* mask  = (const float*)d_in[1];
    const float* W_in  = (const float*)d_in[2];
    const float* b_in  = (const float*)d_in[3];
    const float* W1    = (const float*)d_in[4];
    const float* b1    = (const float*)d_in[5];
    const float* W2    = (const float*)d_in[6];
    const float* b2    = (const float*)d_in[7];
    const float* W_fin = (const float*)d_in[8];
    const float* b_fin = (const float*)d_in[9];
    float* out = (float*)d_out;

    float *dA0, *dH, *dHr, *dT, *dTr, *dWFP, *dBFP, *dOUT30;
    cudaGetSymbolAddress((void**)&dA0,    g_A0);
    cudaGetSymbolAddress((void**)&dH,     g_H);
    cudaGetSymbolAddress((void**)&dHr,    g_Hr);
    cudaGetSymbolAddress((void**)&dT,     g_T);
    cudaGetSymbolAddress((void**)&dTr,    g_Tr);
    cudaGetSymbolAddress((void**)&dWFP,   g_WFP);
    cudaGetSymbolAddress((void**)&dBFP,   g_BFP);
    cudaGetSymbolAddress((void**)&dOUT30, g_OUT30);

    uint32_t kc0, kc1, kn0, kn1;
    threefry2x32(0u, 1234u, 0u, 0u, kc0, kc1);   // keys[0] -> categorical
    threefry2x32(0u, 1234u, 0u, 1u, kn0, kn1);   // keys[1] -> normal

    const int SMEM = 2 * 32 * 128 * 4 * 2;       // 65536 B (As + Bs, double buffered)
    cudaFuncSetAttribute(sgemm3<false, true>,
                         cudaFuncAttributeMaxDynamicSharedMemorySize, SMEM);
    cudaFuncSetAttribute(sgemm3<true, true>,
                         cudaFuncAttributeMaxDynamicSharedMemorySize, SMEM);
    cudaFuncSetAttribute(sgemm3<false, false>,
                         cudaFuncAttributeMaxDynamicSharedMemorySize, SMEM);

    prep_kernel<<<(BB * 2 * DD + 255) / 256, 256>>>(x, mask);
    gather_kernel<<<(HH * NOUT + NOUT + 255) / 256, 256>>>(W_fin, b_fin);

    dim3 blk(128);
    dim3 g1(HH / 128, BB / 64);                  // 4 x 64 = 256 CTAs
    // h = A0 @ W_in + b_in ; also relu(h)
    sgemm3<false, true><<<g1, blk, SMEM>>>(dA0, W_in, b_in, dH, dHr, HH, 2 * DD);
    for (int l = 0; l < LL; l++) {
        // t = relu(h) @ W1 + b1 ; also relu(t)
        sgemm3<false, true><<<g1, blk, SMEM>>>(dHr, W1 + (size_t)l * HH * HH, b1 + l * HH, dT, dTr, HH, HH);
        // h = h + relu(t) @ W2 + b2 ; also relu(h)
        sgemm3<true, true><<<g1, blk, SMEM>>>(dTr, W2 + (size_t)l * HH * HH, b2 + l * HH, dH, dHr, HH, HH);
    }
    // final pruned GEMM
    dim3 g2(NOUT / 128, BB / 64);                // 60 x 64 = 3840 CTAs
    sgemm3<false, false><<<g2, blk, SMEM>>>(dH, dWFP, dBFP, dOUT30, nullptr, NOUT, HH);

    fused_tail<<<(BB * DD + 255) / 256, 256>>>(x, mask, out, kc0, kc1, kn0, kn1);
}

// round 7
// speedup vs baseline: 1.1835x; 1.1446x over previous
#include <cuda_runtime.h>
#include <cuda_bf16.h>
#include <cstdint>
#include <math.h>

// ---------------- problem constants ----------------
#define BB   4096
#define DD   256
#define HH   512
#define KK   10
#define HEADN 94
#define LL   4
#define SS   10
#define NLG  (DD * 10)     // 2560 logit cols
#define NMS  (DD * 20)     // 5120 mean/scale cols

typedef unsigned long long ull;

// ---------------- scratch ----------------
__device__ float g_H[BB * HH];                 // hidden state
__device__ float g_T[BB * HH];                 // temp
__device__ float g_WLG[HH * NLG];              // gathered logits weights [k][n]
__device__ float g_BLG[NLG];
__device__ float g_LG[(size_t)BB * NLG];       // logits (+bias)
__device__ __nv_bfloat16 g_Hh[BB * HH];        // bf16 split of H
__device__ __nv_bfloat16 g_Hl[BB * HH];
__device__ __nv_bfloat16 g_WBTh[NMS * HH];     // bf16 split of mean/scale W, [n][k]
__device__ __nv_bfloat16 g_WBTl[NMS * HH];
__device__ float g_BMS[NMS];
__device__ float g_MS[(size_t)BB * NMS];       // means/scales (+bias)

// ---------------- f32x2 helpers ----------------
__device__ __forceinline__ ull pack2(float lo, float hi) {
    ull r; asm("mov.b64 %0, {%1, %2};" : "=l"(r) : "f"(lo), "f"(hi)); return r;
}
__device__ __forceinline__ ull fma2(ull a, ull b, ull c) {
    ull r; asm("fma.rn.f32x2 %0, %1, %2, %3;" : "=l"(r) : "l"(a), "l"(b), "l"(c)); return r;
}
__device__ __forceinline__ void unpack2(ull v, float& lo, float& hi) {
    asm("mov.b64 {%0, %1}, %2;" : "=f"(lo), "=f"(hi) : "l"(v));
}

// ---------------- cp.async ----------------
__device__ __forceinline__ void cp_async16(uint32_t dst, const void* src) {
    asm volatile("cp.async.cg.shared.global [%0], [%1], 16;" :: "r"(dst), "l"(src));
}
__device__ __forceinline__ void cp_commit() { asm volatile("cp.async.commit_group;"); }
__device__ __forceinline__ void cp_wait0()  { asm volatile("cp.async.wait_group 0;"); }
__device__ __forceinline__ void cp_wait1()  { asm volatile("cp.async.wait_group 1;"); }

// ---------------- mma / ldmatrix ----------------
__device__ __forceinline__ void ldsm4(uint32_t* r, uint32_t addr) {
    asm volatile("ldmatrix.sync.aligned.m8n8.x4.shared.b16 {%0,%1,%2,%3}, [%4];"
                 : "=r"(r[0]), "=r"(r[1]), "=r"(r[2]), "=r"(r[3]) : "r"(addr));
}
__device__ __forceinline__ void mma_bf16(float* c, const uint32_t* a, uint32_t b0, uint32_t b1) {
    asm volatile("mma.sync.aligned.m16n8k16.row.col.f32.bf16.bf16.f32 "
                 "{%0,%1,%2,%3}, {%4,%5,%6,%7}, {%8,%9}, {%0,%1,%2,%3};"
                 : "+f"(c[0]), "+f"(c[1]), "+f"(c[2]), "+f"(c[3])
                 : "r"(a[0]), "r"(a[1]), "r"(a[2]), "r"(a[3]), "r"(b0), "r"(b1));
}

// ---------------- threefry2x32 (bit-exact JAX) ----------------
__host__ __device__ __forceinline__ uint32_t rotl32(uint32_t x, int r) {
#if defined(__CUDA_ARCH__)
    return __funnelshift_l(x, x, r);
#else
    return (x << r) | (x >> (32 - r));
#endif
}

__host__ __device__ __forceinline__ void threefry2x32(
    uint32_t k0, uint32_t k1, uint32_t x0, uint32_t x1,
    uint32_t& o0, uint32_t& o1)
{
    uint32_t k2 = k0 ^ k1 ^ 0x1BD11BDAu;
    x0 += k0; x1 += k1;
    x0 += x1; x1 = rotl32(x1, 13); x1 ^= x0;
    x0 += x1; x1 = rotl32(x1, 15); x1 ^= x0;
    x0 += x1; x1 = rotl32(x1, 26); x1 ^= x0;
    x0 += x1; x1 = rotl32(x1, 6);  x1 ^= x0;
    x0 += k1; x1 += k2 + 1u;
    x0 += x1; x1 = rotl32(x1, 17); x1 ^= x0;
    x0 += x1; x1 = rotl32(x1, 29); x1 ^= x0;
    x0 += x1; x1 = rotl32(x1, 16); x1 ^= x0;
    x0 += x1; x1 = rotl32(x1, 24); x1 ^= x0;
    x0 += k2; x1 += k0 + 2u;
    x0 += x1; x1 = rotl32(x1, 13); x1 ^= x0;
    x0 += x1; x1 = rotl32(x1, 15); x1 ^= x0;
    x0 += x1; x1 = rotl32(x1, 26); x1 ^= x0;
    x0 += x1; x1 = rotl32(x1, 6);  x1 ^= x0;
    x0 += k0; x1 += k1 + 3u;
    x0 += x1; x1 = rotl32(x1, 17); x1 ^= x0;
    x0 += x1; x1 = rotl32(x1, 29); x1 ^= x0;
    x0 += x1; x1 = rotl32(x1, 16); x1 ^= x0;
    x0 += x1; x1 = rotl32(x1, 24); x1 ^= x0;
    x0 += k1; x1 += k2 + 4u;
    x0 += x1; x1 = rotl32(x1, 13); x1 ^= x0;
    x0 += x1; x1 = rotl32(x1, 15); x1 ^= x0;
    x0 += x1; x1 = rotl32(x1, 26); x1 ^= x0;
    x0 += x1; x1 = rotl32(x1, 6);  x1 ^= x0;
    x0 += k2; x1 += k0 + 5u;
    o0 = x0; o1 = x1;
}

__device__ __forceinline__ uint32_t tf_bits(uint32_t k0, uint32_t k1, uint32_t idx) {
    uint32_t o0, o1;
    threefry2x32(k0, k1, 0u, idx, o0, o1);
    return o0 ^ o1;
}

// ---------------- XLA-exact erfinv ----------------
__device__ __forceinline__ float erfinv_xla(float x) {
    float w = -logf((1.0f - x) * (1.0f + x));
    float p;
    if (w < 5.0f) {
        w -= 2.5f;
        p = 2.81022636e-08f;
        p = fmaf(p, w, 3.43273939e-07f);
        p = fmaf(p, w, -3.5233877e-06f);
        p = fmaf(p, w, -4.39150654e-06f);
        p = fmaf(p, w, 0.00021858087f);
        p = fmaf(p, w, -0.00125372503f);
        p = fmaf(p, w, -0.00417768164f);
        p = fmaf(p, w, 0.246640727f);
        p = fmaf(p, w, 1.50140941f);
    } else {
        w = sqrtf(w) - 3.0f;
        p = -0.000200214257f;
        p = fmaf(p, w, 0.000100950558f);
        p = fmaf(p, w, 0.00134934322f);
        p = fmaf(p, w, -0.00367342844f);
        p = fmaf(p, w, 0.00573950773f);
        p = fmaf(p, w, -0.0076224613f);
        p = fmaf(p, w, 0.00943887047f);
        p = fmaf(p, w, 1.00167406f);
        p = fmaf(p, w, 2.83297682f);
    }
    return p * x;
}

__device__ __forceinline__ float bits_to_unit(uint32_t b) {
    return __uint_as_float((b >> 9) | 0x3F800000u) - 1.0f;
}

__device__ __forceinline__ float gumbel_from_bits(uint32_t bits) {
    const float TINY = 1.17549435e-38f;
    float f = bits_to_unit(bits);
    float u = fmaxf(TINY, f + TINY);
    return -logf(-logf(u));
}

// ---------------- gather kernels ----------------
// logits weights: W_LG[k][n], n = d*10 + j -> W_fin col d*94 + j
__global__ void gather_lg(const float* __restrict__ Wf, const float* __restrict__ bf) {
    int t = blockIdx.x * blockDim.x + threadIdx.x;
    const int total = HH * NLG;
    if (t < total) {
        int n = t % NLG;
        int k = t / NLG;
        int d = n / 10, j = n - d * 10;
        g_WLG[t] = Wf[(size_t)k * (DD * HEADN) + d * HEADN + j];
    } else if (t < total + NLG) {
        int n = t - total;
        int d = n / 10, j = n - d * 10;
        g_BLG[n] = bf[d * HEADN + j];
    }
}

// mean/scale weights, bf16-split, transposed [n][k]; n = d*20 + r -> col d*94 + 10 + r
__global__ void gather_ms(const float* __restrict__ Wf, const float* __restrict__ bf) {
    int t = blockIdx.x * blockDim.x + threadIdx.x;
    const int total = NMS * HH;
    if (t < total) {
        int k = t % HH;
        int n = t / HH;
        int d = n / 20, r = n - d * 20;
        float w = Wf[(size_t)k * (DD * HEADN) + d * HEADN + 10 + r];
        __nv_bfloat16 wh = __float2bfloat16(w);
        g_WBTh[t] = wh;
        g_WBTl[t] = __float2bfloat16(w - __bfloat162float(wh));
    } else if (t < total + NMS) {
        int n = t - total;
        int d = n / 20, r = n - d * 20;
        g_BMS[n] = bf[d * HEADN + 10 + r];
    }
}

// split H into bf16 hi/lo
__global__ void h2bf() {
    int t = blockIdx.x * blockDim.x + threadIdx.x;
    if (t >= BB * HH) return;
    float v = g_H[t];
    __nv_bfloat16 hh = __float2bfloat16(v);
    g_Hh[t] = hh;
    g_Hl[t] = __float2bfloat16(v - __bfloat162float(hh));
}

// ---------------- exact fp32 SGEMM (R4 config: 64x128, BK=16, f32x2) ----------------
template <bool RELU_A, bool ADD_C, bool PREP>
__global__ __launch_bounds__(128, 3) void sgemm_f32x2(
    const float* __restrict__ A, const float* __restrict__ Xm,
    const float* __restrict__ Bm,
    const float* __restrict__ bias, float* __restrict__ C,
    int N, int Kd)
{
    __shared__ float As[2][16][68];
    __shared__ float Bs[2][16][128];

    const int t  = threadIdx.x;
    const int bm = blockIdx.y * 64;
    const int bn = blockIdx.x * 128;
    const int tx = t & 15;
    const int ty = t >> 4;

    const int arow = t >> 1;
    const int ak   = (t & 1) * 8;
    const int brow = t >> 5;
    const int bcol = (t & 31) * 4;

    ull acc2[8][4];
#pragma unroll
    for (int i = 0; i < 8; i++)
#pragma unroll
        for (int j = 0; j < 4; j++) acc2[i][j] = 0ull;

    float4 aR0, aR1, bR[4];

    auto loadG = [&](int k0) {
        if (PREP) {
            int col0 = k0 + ak;
            const float* xrow = A  + (size_t)(bm + arow) * DD;
            const float* mrow = Xm + (size_t)(bm + arow) * DD;
            if (col0 < DD) {
                float4 xv = *reinterpret_cast<const float4*>(xrow + col0);
                float4 mv = *reinterpret_cast<const float4*>(mrow + col0);
                aR0 = make_float4(xv.x * mv.x, xv.y * mv.y, xv.z * mv.z, xv.w * mv.w);
                xv = *reinterpret_cast<const float4*>(xrow + col0 + 4);
                mv = *reinterpret_cast<const float4*>(mrow + col0 + 4);
                aR1 = make_float4(xv.x * mv.x, xv.y * mv.y, xv.z * mv.z, xv.w * mv.w);
            } else {
                aR0 = *reinterpret_cast<const float4*>(mrow + col0 - DD);
                aR1 = *reinterpret_cast<const float4*>(mrow + col0 - DD + 4);
            }
        } else {
            const float* Ap = A + (size_t)(bm + arow) * Kd + k0 + ak;
            aR0 = *reinterpret_cast<const float4*>(Ap);
            aR1 = *reinterpret_cast<const float4*>(Ap + 4);
            if (RELU_A) {
                aR0.x = fmaxf(aR0.x, 0.f); aR0.y = fmaxf(aR0.y, 0.f);
                aR0.z = fmaxf(aR0.z, 0.f); aR0.w = fmaxf(aR0.w, 0.f);
                aR1.x = fmaxf(aR1.x, 0.f); aR1.y = fmaxf(aR1.y, 0.f);
                aR1.z = fmaxf(aR1.z, 0.f); aR1.w = fmaxf(aR1.w, 0.f);
            }
        }
#pragma unroll
        for (int i = 0; i < 4; i++)
            bR[i] = *reinterpret_cast<const float4*>(Bm + (size_t)(k0 + brow + 4 * i) * N + bn + bcol);
    };
    auto storeS = [&](int p) {
        As[p][ak + 0][arow] = aR0.x;
        As[p][ak + 1][arow] = aR0.y;
        As[p][ak + 2][arow] = aR0.z;
        As[p][ak + 3][arow] = aR0.w;
        As[p][ak + 4][arow] = aR1.x;
        As[p][ak + 5][arow] = aR1.y;
        As[p][ak + 6][arow] = aR1.z;
        As[p][ak + 7][arow] = aR1.w;
#pragma unroll
        for (int i = 0; i < 4; i++)
            *reinterpret_cast<float4*>(&Bs[p][brow + 4 * i][bcol]) = bR[i];
    };

    loadG(0);
    storeS(0);
    __syncthreads();

    const int T = Kd >> 4;
    int p = 0;
#pragma unroll 1
    for (int tk = 0; tk < T; tk++) {
        if (tk + 1 < T) loadG((tk + 1) << 4);
#pragma unroll
        for (int kk = 0; kk < 16; kk++) {
            float a[8];
            *reinterpret_cast<float4*>(a)     = *reinterpret_cast<const float4*>(&As[p][kk][ty * 8]);
            *reinterpret_cast<float4*>(a + 4) = *reinterpret_cast<const float4*>(&As[p][kk][ty * 8 + 4]);
            ulonglong2 bq0 = *reinterpret_cast<const ulonglong2*>(&Bs[p][kk][tx * 8]);
            ulonglong2 bq1 = *reinterpret_cast<const ulonglong2*>(&Bs[p][kk][tx * 8 + 4]);
#pragma unroll
            for (int i = 0; i < 8; i++) {
                ull a2 = pack2(a[i], a[i]);
                acc2[i][0] = fma2(a2, bq0.x, acc2[i][0]);
                acc2[i][1] = fma2(a2, bq0.y, acc2[i][1]);
                acc2[i][2] = fma2(a2, bq1.x, acc2[i][2]);
                acc2[i][3] = fma2(a2, bq1.y, acc2[i][3]);
            }
        }
        if (tk + 1 < T) {
            storeS(p ^ 1);
            __syncthreads();
            p ^= 1;
        }
    }

    float4 bia0 = *reinterpret_cast<const float4*>(bias + bn + tx * 8);
    float4 bia1 = *reinterpret_cast<const float4*>(bias + bn + tx * 8 + 4);
#pragma unroll
    for (int i = 0; i < 8; i++) {
        float* crow = C + (size_t)(bm + ty * 8 + i) * N + bn + tx * 8;
        float v[8];
        unpack2(acc2[i][0], v[0], v[1]);
        unpack2(acc2[i][1], v[2], v[3]);
        unpack2(acc2[i][2], v[4], v[5]);
        unpack2(acc2[i][3], v[6], v[7]);
        float4 r0, r1;
        r0.x = v[0] + bia0.x; r0.y = v[1] + bia0.y;
        r0.z = v[2] + bia0.z; r0.w = v[3] + bia0.w;
        r1.x = v[4] + bia1.x; r1.y = v[5] + bia1.y;
        r1.z = v[6] + bia1.z; r1.w = v[7] + bia1.w;
        if (ADD_C) {
            float4 c0 = *reinterpret_cast<const float4*>(crow);
            float4 c1 = *reinterpret_cast<const float4*>(crow + 4);
            r0.x += c0.x; r0.y += c0.y; r0.z += c0.z; r0.w += c0.w;
            r1.x += c1.x; r1.y += c1.y; r1.z += c1.z; r1.w += c1.w;
        }
        *reinterpret_cast<float4*>(crow)     = r0;
        *reinterpret_cast<float4*>(crow + 4) = r1;
    }
}

// ---------------- bf16-split HMMA GEMM for means/scales ----------------
// C[4096, 5120] = H @ W_ms^T + b_ms,   H split in g_Hh/g_Hl, W in g_WBTh/g_WBTl.
// CTA tile 64(M) x 64(N), 4 warps (each 16x64), BK=16, double-buffered cp.async.
__global__ __launch_bounds__(128) void musc_mma() {
    // smem: per buffer, 4 tiles (Ah, Al, Bh, Bl), each 64 rows x 48B (16 bf16 + pad)
    __shared__ __align__(16) char smc[2 * 4 * 64 * 48];

    const int t = threadIdx.x;
    const int w = t >> 5;
    const int l = t & 31;
    const int bn = blockIdx.x * 64;
    const int bm = blockIdx.y * 64;

    const int tile = t >> 5;          // this thread fills tile 0..3
    const int r2   = t & 31;          // fills rows 2*r2, 2*r2+1

    const uint32_t smbase = (uint32_t)__cvta_generic_to_shared(smc);

    const __nv_bfloat16* gsrc =
        (tile == 0) ? g_Hh : (tile == 1) ? g_Hl : (tile == 2) ? g_WBTh : g_WBTl;
    const int gbase = (tile < 2) ? bm : bn;

    auto issue = [&](int k0, int p) {
        uint32_t dbase = smbase + (uint32_t)(p * 12288 + tile * 3072);
#pragma unroll
        for (int rr = 0; rr < 2; rr++) {
            int row = r2 * 2 + rr;
            const __nv_bfloat16* s = gsrc + (size_t)(gbase + row) * HH + k0;
            uint32_t dst = dbase + (uint32_t)(row * 48);
            cp_async16(dst, s);
            cp_async16(dst + 16, reinterpret_cast<const char*>(s) + 16);
        }
    };

    // fragment addresses (lane-dependent), relative to buffer base
    const uint32_t a_off  = (uint32_t)((w * 16 + (l & 15)) * 48 + ((l >> 4) << 4));
    const uint32_t b_row  = (uint32_t)((l & 7) + ((l >> 4) & 1) * 8);
    const uint32_t b_koff = (uint32_t)(((l >> 3) & 1) << 4);

    float acc[8][4];
#pragma unroll
    for (int i = 0; i < 8; i++)
#pragma unroll
        for (int j = 0; j < 4; j++) acc[i][j] = 0.0f;

    issue(0, 0);
    cp_commit();

    const int T = HH / 16;  // 32
    int p = 0;
#pragma unroll 1
    for (int tk = 0; tk < T; tk++) {
        if (tk + 1 < T) {
            issue((tk + 1) * 16, p ^ 1);
            cp_commit();
            cp_wait1();
        } else {
            cp_wait0();
        }
        __syncthreads();

        uint32_t base = smbase + (uint32_t)(p * 12288);
        uint32_t ah[4], al[4];
        ldsm4(ah, base + a_off);            // Ah tile at offset 0
        ldsm4(al, base + 3072 + a_off);     // Al tile
#pragma unroll
        for (int q = 0; q < 4; q++) {
            uint32_t boff = (uint32_t)((q * 16 + b_row) * 48) + b_koff;
            uint32_t bh[4], bl[4];
            ldsm4(bh, base + 6144 + boff);  // Bh tile
            ldsm4(bl, base + 9216 + boff);  // Bl tile
            // nb = 2q
            mma_bf16(acc[2 * q],     ah, bh[0], bh[1]);
            mma_bf16(acc[2 * q],     ah, bl[0], bl[1]);
            mma_bf16(acc[2 * q],     al, bh[0], bh[1]);
            // nb = 2q+1
            mma_bf16(acc[2 * q + 1], ah, bh[2], bh[3]);
            mma_bf16(acc[2 * q + 1], ah, bl[2], bl[3]);
            mma_bf16(acc[2 * q + 1], al, bh[2], bh[3]);
        }
        __syncthreads();
        p ^= 1;
    }

    // epilogue: lane l -> rows g, g+8; cols 2t, 2t+1 of each 8-wide n-block
    const int g  = l >> 2;
    const int tt = l & 3;
#pragma unroll
    for (int nb = 0; nb < 8; nb++) {
        int n = bn + nb * 8 + tt * 2;
        float2 bia = *reinterpret_cast<const float2*>(g_BMS + n);
        int m0 = bm + w * 16 + g;
        float2 v0 = make_float2(acc[nb][0] + bia.x, acc[nb][1] + bia.y);
        float2 v1 = make_float2(acc[nb][2] + bia.x, acc[nb][3] + bia.y);
        *reinterpret_cast<float2*>(g_MS + (size_t)m0 * NMS + n)       = v0;
        *reinterpret_cast<float2*>(g_MS + (size_t)(m0 + 8) * NMS + n) = v1;
    }
}

// ---------------- fused tail ----------------
__global__ void fused_tail(const float* __restrict__ x, const float* __restrict__ mask,
                           float* __restrict__ out,
                           uint32_t kc0, uint32_t kc1, uint32_t kn0, uint32_t kn1)
{
    int t = blockIdx.x * blockDim.x + threadIdx.x;
    if (t >= BB * DD) return;
    int b = t >> 8;
    int d = t & (DD - 1);

    const float* lrow = g_LG + (size_t)b * NLG + d * 10;
    const float* mrow = g_MS + (size_t)b * NMS + d * 20;
    float lg[KK], mu[KK], sc[KK];
#pragma unroll
    for (int j = 0; j < KK; j++) lg[j] = lrow[j];
#pragma unroll
    for (int j = 0; j < KK; j++) mu[j] = mrow[j];
#pragma unroll
    for (int j = 0; j < KK; j++) {
        float v = mrow[10 + j];
        sc[j] = fmaxf(v, 0.0f) + log1pf(expf(-fabsf(v))) + 0.001f;
    }
    float q  = 1.0f - mask[t];
    float xu = x[t] * q;

    float mx = lg[0];
#pragma unroll
    for (int j = 1; j < KK; j++) mx = fmaxf(mx, lg[j]);
    float se = 0.0f;
#pragma unroll
    for (int j = 0; j < KK; j++) se += expf(lg[j] - mx);
    float lse = logf(se);

    float term[KK];
    float m2 = -1e30f;
#pragma unroll
    for (int j = 0; j < KK; j++) {
        float z   = (xu - mu[j]) / sc[j];
        float cll = -0.5f * z * z - logf(sc[j]) - 0.9189385332046727f;
        term[j] = (lg[j] - mx - lse) + cll;
        m2 = fmaxf(m2, term[j]);
    }
    float s2 = 0.0f;
#pragma unroll
    for (int j = 0; j < KK; j++) s2 += expf(term[j] - m2);
    out[t] = (m2 + logf(s2)) * q;

    float pm = 0.0f;
#pragma unroll
    for (int j = 0; j < KK; j++) pm += (expf(lg[j] - mx) / se) * mu[j];
    out[BB * DD + SS * BB * DD + t] = pm * q;

    float* smp = out + BB * DD;

#pragma unroll 1
    for (int s = 0; s < SS; s++) {
        uint32_t idx_e = (uint32_t)(s * BB + b) * DD + (uint32_t)d;
        uint32_t base  = idx_e * KK;
        float best = -1e30f;
        int a = 0;
#pragma unroll
        for (int j = 0; j < KK; j++) {
            uint32_t bits = tf_bits(kc0, kc1, base + j);
            float v = lg[j] + gumbel_from_bits(bits);
            if (v > best) { best = v; a = j; }
        }
        float mua = 0.f, sca = 0.f;
#pragma unroll
        for (int j = 0; j < KK; j++) {
            if (a == j) { mua = mu[j]; sca = sc[j]; }
        }
        uint32_t ebits = tf_bits(kn0, kn1, idx_e);
        const float LO = -0.99999994f;
        float u = fmaxf(LO, fmaf(bits_to_unit(ebits), 2.0f, LO));
        float eps = 1.41421356237309515f * erfinv_xla(u);
        smp[(b * SS + s) * DD + d] = (mua + sca * eps) * q;
    }
}

// ---------------- launch ----------------
extern "C" void kernel_launch(void* const* d_in, const int* in_sizes, int n_in,
                              void* d_out, int out_size)
{
    const float* x     = (const float*)d_in[0];
    const float* mask  = (const float*)d_in[1];
    const float* W_in  = (const float*)d_in[2];
    const float* b_in  = (const float*)d_in[3];
    const float* W1    = (const float*)d_in[4];
    const float* b1    = (const float*)d_in[5];
    const float* W2    = (const float*)d_in[6];
    const float* b2    = (const float*)d_in[7];
    const float* W_fin = (const float*)d_in[8];
    const float* b_fin = (const float*)d_in[9];
    float* out = (float*)d_out;

    float *dH, *dT, *dWLG, *dBLG, *dLG;
    cudaGetSymbolAddress((void**)&dH,   g_H);
    cudaGetSymbolAddress((void**)&dT,   g_T);
    cudaGetSymbolAddress((void**)&dWLG, g_WLG);
    cudaGetSymbolAddress((void**)&dBLG, g_BLG);
    cudaGetSymbolAddress((void**)&dLG,  g_LG);

    uint32_t kc0, kc1, kn0, kn1;
    threefry2x32(0u, 1234u, 0u, 0u, kc0, kc1);   // keys[0] -> categorical
    threefry2x32(0u, 1234u, 0u, 1u, kn0, kn1);   // keys[1] -> normal

    gather_lg<<<(HH * NLG + NLG + 255) / 256, 256>>>(W_fin, b_fin);
    gather_ms<<<(NMS * HH + NMS + 255) / 256, 256>>>(W_fin, b_fin);

    dim3 blk(128);
    dim3 g1(HH / 128, BB / 64);                  // 4 x 64 = 256 CTAs
    // h = concat(x*mask, mask) @ W_in + b_in
    sgemm_f32x2<false, false, true><<<g1, blk>>>(x, mask, W_in, b_in, dH, HH, 2 * DD);
    for (int l = 0; l < LL; l++) {
        sgemm_f32x2<true, false, false><<<g1, blk>>>(dH, nullptr, W1 + (size_t)l * HH * HH, b1 + l * HH, dT, HH, HH);
        sgemm_f32x2<true, true,  false><<<g1, blk>>>(dT, nullptr, W2 + (size_t)l * HH * HH, b2 + l * HH, dH, HH, HH);
    }

    // split H into bf16 hi/lo
    h2bf<<<(BB * HH + 255) / 256, 256>>>();

    // logits: exact fp32 GEMM (argmax-safe)
    dim3 g2(NLG / 128, BB / 64);                 // 20 x 64 = 1280 CTAs
    sgemm_f32x2<false, false, false><<<g2, blk>>>(dH, nullptr, dWLG, dBLG, dLG, NLG, HH);

    // means/scales: bf16-split tensor-core GEMM
    dim3 g3(NMS / 64, BB / 64);                  // 80 x 64 = 5120 CTAs
    musc_mma<<<g3, blk>>>();

    fused_tail<<<(BB * DD + 255) / 256, 256>>>(x, mask, out, kc0, kc1, kn0, kn1);
}

// round 8
// speedup vs baseline: 1.2437x; 1.0509x over previous
#include <cuda_runtime.h>
#include <cuda_bf16.h>
#include <cstdint>
#include <math.h>

// ---------------- problem constants ----------------
#define BB   4096
#define DD   256
#define HH   512
#define KK   10
#define HEADN 94
#define LL   4
#define SS   10
#define NLG  (DD * 10)     // 2560 logit cols
#define NMS  (DD * 20)     // 5120 mean/scale cols

typedef unsigned long long ull;

// ---------------- scratch ----------------
__device__ float g_H[BB * HH];                 // hidden state
__device__ float g_T[BB * HH];                 // temp
__device__ float g_WLG[HH * NLG];              // gathered logits weights [k][n]
__device__ float g_BLG[NLG];
__device__ float g_LG[(size_t)BB * NLG];       // logits (+bias)
__device__ __nv_bfloat16 g_Hh[BB * HH];        // bf16 split of H
__device__ __nv_bfloat16 g_Hl[BB * HH];
__device__ __nv_bfloat16 g_WBTh[NMS * HH];     // bf16 split of mean/scale W, [n][k]
__device__ __nv_bfloat16 g_WBTl[NMS * HH];
__device__ float g_BMS[NMS];
__device__ float g_MS[(size_t)BB * NMS];       // means/scales (+bias)

// ---------------- f32x2 helpers ----------------
__device__ __forceinline__ ull pack2(float lo, float hi) {
    ull r; asm("mov.b64 %0, {%1, %2};" : "=l"(r) : "f"(lo), "f"(hi)); return r;
}
__device__ __forceinline__ ull fma2(ull a, ull b, ull c) {
    ull r; asm("fma.rn.f32x2 %0, %1, %2, %3;" : "=l"(r) : "l"(a), "l"(b), "l"(c)); return r;
}
__device__ __forceinline__ void unpack2(ull v, float& lo, float& hi) {
    asm("mov.b64 {%0, %1}, %2;" : "=f"(lo), "=f"(hi) : "l"(v));
}

// ---------------- cp.async ----------------
__device__ __forceinline__ void cp_async16(uint32_t dst, const void* src) {
    asm volatile("cp.async.cg.shared.global [%0], [%1], 16;" :: "r"(dst), "l"(src));
}
__device__ __forceinline__ void cp_commit() { asm volatile("cp.async.commit_group;"); }
__device__ __forceinline__ void cp_wait0()  { asm volatile("cp.async.wait_group 0;"); }
__device__ __forceinline__ void cp_wait1()  { asm volatile("cp.async.wait_group 1;"); }

// ---------------- mma / ldmatrix ----------------
__device__ __forceinline__ void ldsm4(uint32_t* r, uint32_t addr) {
    asm volatile("ldmatrix.sync.aligned.m8n8.x4.shared.b16 {%0,%1,%2,%3}, [%4];"
                 : "=r"(r[0]), "=r"(r[1]), "=r"(r[2]), "=r"(r[3]) : "r"(addr));
}
__device__ __forceinline__ void mma_bf16(float* c, const uint32_t* a, uint32_t b0, uint32_t b1) {
    asm volatile("mma.sync.aligned.m16n8k16.row.col.f32.bf16.bf16.f32 "
                 "{%0,%1,%2,%3}, {%4,%5,%6,%7}, {%8,%9}, {%0,%1,%2,%3};"
                 : "+f"(c[0]), "+f"(c[1]), "+f"(c[2]), "+f"(c[3])
                 : "r"(a[0]), "r"(a[1]), "r"(a[2]), "r"(a[3]), "r"(b0), "r"(b1));
}

// ---------------- threefry2x32 (bit-exact JAX) ----------------
__host__ __device__ __forceinline__ uint32_t rotl32(uint32_t x, int r) {
#if defined(__CUDA_ARCH__)
    return __funnelshift_l(x, x, r);
#else
    return (x << r) | (x >> (32 - r));
#endif
}

__host__ __device__ __forceinline__ void threefry2x32(
    uint32_t k0, uint32_t k1, uint32_t x0, uint32_t x1,
    uint32_t& o0, uint32_t& o1)
{
    uint32_t k2 = k0 ^ k1 ^ 0x1BD11BDAu;
    x0 += k0; x1 += k1;
    x0 += x1; x1 = rotl32(x1, 13); x1 ^= x0;
    x0 += x1; x1 = rotl32(x1, 15); x1 ^= x0;
    x0 += x1; x1 = rotl32(x1, 26); x1 ^= x0;
    x0 += x1; x1 = rotl32(x1, 6);  x1 ^= x0;
    x0 += k1; x1 += k2 + 1u;
    x0 += x1; x1 = rotl32(x1, 17); x1 ^= x0;
    x0 += x1; x1 = rotl32(x1, 29); x1 ^= x0;
    x0 += x1; x1 = rotl32(x1, 16); x1 ^= x0;
    x0 += x1; x1 = rotl32(x1, 24); x1 ^= x0;
    x0 += k2; x1 += k0 + 2u;
    x0 += x1; x1 = rotl32(x1, 13); x1 ^= x0;
    x0 += x1; x1 = rotl32(x1, 15); x1 ^= x0;
    x0 += x1; x1 = rotl32(x1, 26); x1 ^= x0;
    x0 += x1; x1 = rotl32(x1, 6);  x1 ^= x0;
    x0 += k0; x1 += k1 + 3u;
    x0 += x1; x1 = rotl32(x1, 17); x1 ^= x0;
    x0 += x1; x1 = rotl32(x1, 29); x1 ^= x0;
    x0 += x1; x1 = rotl32(x1, 16); x1 ^= x0;
    x0 += x1; x1 = rotl32(x1, 24); x1 ^= x0;
    x0 += k1; x1 += k2 + 4u;
    x0 += x1; x1 = rotl32(x1, 13); x1 ^= x0;
    x0 += x1; x1 = rotl32(x1, 15); x1 ^= x0;
    x0 += x1; x1 = rotl32(x1, 26); x1 ^= x0;
    x0 += x1; x1 = rotl32(x1, 6);  x1 ^= x0;
    x0 += k2; x1 += k0 + 5u;
    o0 = x0; o1 = x1;
}

__device__ __forceinline__ uint32_t tf_bits(uint32_t k0, uint32_t k1, uint32_t idx) {
    uint32_t o0, o1;
    threefry2x32(k0, k1, 0u, idx, o0, o1);
    return o0 ^ o1;
}

// ---------------- XLA-exact erfinv ----------------
__device__ __forceinline__ float erfinv_xla(float x) {
    float w = -logf((1.0f - x) * (1.0f + x));
    float p;
    if (w < 5.0f) {
        w -= 2.5f;
        p = 2.81022636e-08f;
        p = fmaf(p, w, 3.43273939e-07f);
        p = fmaf(p, w, -3.5233877e-06f);
        p = fmaf(p, w, -4.39150654e-06f);
        p = fmaf(p, w, 0.00021858087f);
        p = fmaf(p, w, -0.00125372503f);
        p = fmaf(p, w, -0.00417768164f);
        p = fmaf(p, w, 0.246640727f);
        p = fmaf(p, w, 1.50140941f);
    } else {
        w = sqrtf(w) - 3.0f;
        p = -0.000200214257f;
        p = fmaf(p, w, 0.000100950558f);
        p = fmaf(p, w, 0.00134934322f);
        p = fmaf(p, w, -0.00367342844f);
        p = fmaf(p, w, 0.00573950773f);
        p = fmaf(p, w, -0.0076224613f);
        p = fmaf(p, w, 0.00943887047f);
        p = fmaf(p, w, 1.00167406f);
        p = fmaf(p, w, 2.83297682f);
    }
    return p * x;
}

__device__ __forceinline__ float bits_to_unit(uint32_t b) {
    return __uint_as_float((b >> 9) | 0x3F800000u) - 1.0f;
}

__device__ __forceinline__ float gumbel_from_bits(uint32_t bits) {
    const float TINY = 1.17549435e-38f;
    float f = bits_to_unit(bits);
    float u = fmaxf(TINY, f + TINY);
    return -logf(-logf(u));
}

// ---------------- gather kernels ----------------
// logits weights: W_LG[k][n], n = d*10 + j -> W_fin col d*94 + j
__global__ void gather_lg(const float* __restrict__ Wf, const float* __restrict__ bf) {
    int t = blockIdx.x * blockDim.x + threadIdx.x;
    const int total = HH * NLG;
    if (t < total) {
        int n = t % NLG;
        int k = t / NLG;
        int d = n / 10, j = n - d * 10;
        g_WLG[t] = Wf[(size_t)k * (DD * HEADN) + d * HEADN + j];
    } else if (t < total + NLG) {
        int n = t - total;
        int d = n / 10, j = n - d * 10;
        g_BLG[n] = bf[d * HEADN + j];
    }
}

// mean/scale weights: coalesced smem-transpose + bf16 split, out [n][k]
__global__ void gather_ms_t(const float* __restrict__ Wf) {
    __shared__ float tile[32][33];
    int n0 = blockIdx.x * 32;
    int k0 = blockIdx.y * 32;
    int tx = threadIdx.x & 31;
    int ty = threadIdx.x >> 5;      // 0..7
    // read: rows k, cols n (coalesced-ish in n)
#pragma unroll
    for (int i = 0; i < 4; i++) {
        int k = k0 + ty + i * 8;
        int n = n0 + tx;
        int d = n / 20, r = n - d * 20;
        tile[ty + i * 8][tx] = Wf[(size_t)k * (DD * HEADN) + d * HEADN + 10 + r];
    }
    __syncthreads();
    // write: rows n, cols k (coalesced in k)
#pragma unroll
    for (int i = 0; i < 4; i++) {
        int n = n0 + ty + i * 8;
        int k = k0 + tx;
        float w = tile[tx][ty + i * 8];
        __nv_bfloat16 wh = __float2bfloat16(w);
        g_WBTh[(size_t)n * HH + k] = wh;
        g_WBTl[(size_t)n * HH + k] = __float2bfloat16(w - __bfloat162float(wh));
    }
}

__global__ void gather_bms(const float* __restrict__ bf) {
    int n = blockIdx.x * blockDim.x + threadIdx.x;
    if (n >= NMS) return;
    int d = n / 20, r = n - d * 20;
    g_BMS[n] = bf[d * HEADN + 10 + r];
}

// split H into bf16 hi/lo
__global__ void h2bf() {
    int t = blockIdx.x * blockDim.x + threadIdx.x;
    if (t >= BB * HH) return;
    float v = g_H[t];
    __nv_bfloat16 hh = __float2bfloat16(v);
    g_Hh[t] = hh;
    g_Hl[t] = __float2bfloat16(v - __bfloat162float(hh));
}

// ---------------- exact fp32 SGEMM (64x128, BK=16, f32x2) ----------------
template <bool RELU_A, bool ADD_C, bool PREP>
__global__ __launch_bounds__(128, 3) void sgemm_f32x2(
    const float* __restrict__ A, const float* __restrict__ Xm,
    const float* __restrict__ Bm,
    const float* __restrict__ bias, float* __restrict__ C,
    int N, int Kd)
{
    __shared__ float As[2][16][68];
    __shared__ float Bs[2][16][128];

    const int t  = threadIdx.x;
    const int bm = blockIdx.y * 64;
    const int bn = blockIdx.x * 128;
    const int tx = t & 15;
    const int ty = t >> 4;

    const int arow = t >> 1;
    const int ak   = (t & 1) * 8;
    const int brow = t >> 5;
    const int bcol = (t & 31) * 4;

    ull acc2[8][4];
#pragma unroll
    for (int i = 0; i < 8; i++)
#pragma unroll
        for (int j = 0; j < 4; j++) acc2[i][j] = 0ull;

    float4 aR0, aR1, bR[4];

    auto loadG = [&](int k0) {
        if (PREP) {
            int col0 = k0 + ak;
            const float* xrow = A  + (size_t)(bm + arow) * DD;
            const float* mrow = Xm + (size_t)(bm + arow) * DD;
            if (col0 < DD) {
                float4 xv = *reinterpret_cast<const float4*>(xrow + col0);
                float4 mv = *reinterpret_cast<const float4*>(mrow + col0);
                aR0 = make_float4(xv.x * mv.x, xv.y * mv.y, xv.z * mv.z, xv.w * mv.w);
                xv = *reinterpret_cast<const float4*>(xrow + col0 + 4);
                mv = *reinterpret_cast<const float4*>(mrow + col0 + 4);
                aR1 = make_float4(xv.x * mv.x, xv.y * mv.y, xv.z * mv.z, xv.w * mv.w);
            } else {
                aR0 = *reinterpret_cast<const float4*>(mrow + col0 - DD);
                aR1 = *reinterpret_cast<const float4*>(mrow + col0 - DD + 4);
            }
        } else {
            const float* Ap = A + (size_t)(bm + arow) * Kd + k0 + ak;
            aR0 = *reinterpret_cast<const float4*>(Ap);
            aR1 = *reinterpret_cast<const float4*>(Ap + 4);
            if (RELU_A) {
                aR0.x = fmaxf(aR0.x, 0.f); aR0.y = fmaxf(aR0.y, 0.f);
                aR0.z = fmaxf(aR0.z, 0.f); aR0.w = fmaxf(aR0.w, 0.f);
                aR1.x = fmaxf(aR1.x, 0.f); aR1.y = fmaxf(aR1.y, 0.f);
                aR1.z = fmaxf(aR1.z, 0.f); aR1.w = fmaxf(aR1.w, 0.f);
            }
        }
#pragma unroll
        for (int i = 0; i < 4; i++)
            bR[i] = *reinterpret_cast<const float4*>(Bm + (size_t)(k0 + brow + 4 * i) * N + bn + bcol);
    };
    auto storeS = [&](int p) {
        As[p][ak + 0][arow] = aR0.x;
        As[p][ak + 1][arow] = aR0.y;
        As[p][ak + 2][arow] = aR0.z;
        As[p][ak + 3][arow] = aR0.w;
        As[p][ak + 4][arow] = aR1.x;
        As[p][ak + 5][arow] = aR1.y;
        As[p][ak + 6][arow] = aR1.z;
        As[p][ak + 7][arow] = aR1.w;
#pragma unroll
        for (int i = 0; i < 4; i++)
            *reinterpret_cast<float4*>(&Bs[p][brow + 4 * i][bcol]) = bR[i];
    };

    loadG(0);
    storeS(0);
    __syncthreads();

    const int T = Kd >> 4;
    int p = 0;
#pragma unroll 1
    for (int tk = 0; tk < T; tk++) {
        if (tk + 1 < T) loadG((tk + 1) << 4);
#pragma unroll
        for (int kk = 0; kk < 16; kk++) {
            float a[8];
            *reinterpret_cast<float4*>(a)     = *reinterpret_cast<const float4*>(&As[p][kk][ty * 8]);
            *reinterpret_cast<float4*>(a + 4) = *reinterpret_cast<const float4*>(&As[p][kk][ty * 8 + 4]);
            ulonglong2 bq0 = *reinterpret_cast<const ulonglong2*>(&Bs[p][kk][tx * 8]);
            ulonglong2 bq1 = *reinterpret_cast<const ulonglong2*>(&Bs[p][kk][tx * 8 + 4]);
#pragma unroll
            for (int i = 0; i < 8; i++) {
                ull a2 = pack2(a[i], a[i]);
                acc2[i][0] = fma2(a2, bq0.x, acc2[i][0]);
                acc2[i][1] = fma2(a2, bq0.y, acc2[i][1]);
                acc2[i][2] = fma2(a2, bq1.x, acc2[i][2]);
                acc2[i][3] = fma2(a2, bq1.y, acc2[i][3]);
            }
        }
        if (tk + 1 < T) {
            storeS(p ^ 1);
            __syncthreads();
            p ^= 1;
        }
    }

    float4 bia0 = *reinterpret_cast<const float4*>(bias + bn + tx * 8);
    float4 bia1 = *reinterpret_cast<const float4*>(bias + bn + tx * 8 + 4);
#pragma unroll
    for (int i = 0; i < 8; i++) {
        float* crow = C + (size_t)(bm + ty * 8 + i) * N + bn + tx * 8;
        float v[8];
        unpack2(acc2[i][0], v[0], v[1]);
        unpack2(acc2[i][1], v[2], v[3]);
        unpack2(acc2[i][2], v[4], v[5]);
        unpack2(acc2[i][3], v[6], v[7]);
        float4 r0, r1;
        r0.x = v[0] + bia0.x; r0.y = v[1] + bia0.y;
        r0.z = v[2] + bia0.z; r0.w = v[3] + bia0.w;
        r1.x = v[4] + bia1.x; r1.y = v[5] + bia1.y;
        r1.z = v[6] + bia1.z; r1.w = v[7] + bia1.w;
        if (ADD_C) {
            float4 c0 = *reinterpret_cast<const float4*>(crow);
            float4 c1 = *reinterpret_cast<const float4*>(crow + 4);
            r0.x += c0.x; r0.y += c0.y; r0.z += c0.z; r0.w += c0.w;
            r1.x += c1.x; r1.y += c1.y; r1.z += c1.z; r1.w += c1.w;
        }
        *reinterpret_cast<float4*>(crow)     = r0;
        *reinterpret_cast<float4*>(crow + 4) = r1;
    }
}

// ---------------- bf16-split HMMA GEMM v2 ----------------
// C[4096, 5120] = H @ W_ms^T + b_ms.  CTA 128x128, 8 warps (4M x 2N),
// warp tile 32x64, BK=32, double-buffered cp.async smem (80KB dynamic).
// Tile layout per buffer: Ah(0) Al(10240) Bh(20480) Bl(30720); row stride 80B.
__global__ __launch_bounds__(256, 2) void musc_mma2() {
    extern __shared__ char smc[];
    const uint32_t smbase = (uint32_t)__cvta_generic_to_shared(smc);

    const int t = threadIdx.x;
    const int w = t >> 5;
    const int l = t & 31;
    const int wm = w & 3;          // 0..3 (M)
    const int wn = w >> 2;         // 0..1 (N)
    const int bn = blockIdx.x * 128;
    const int bm = blockIdx.y * 128;

    // fill: tile = t>>6 (0..3), 64 threads/tile, 2 rows each, 4 cp16/row
    const int tile = t >> 6;
    const int sub  = t & 63;
    const __nv_bfloat16* gsrc =
        (tile == 0) ? g_Hh : (tile == 1) ? g_Hl : (tile == 2) ? g_WBTh : g_WBTl;
    const int gbase = (tile < 2) ? bm : bn;

    auto issue = [&](int k0, int p) {
        uint32_t dbase = smbase + (uint32_t)(p * 40960 + tile * 10240);
#pragma unroll
        for (int rr = 0; rr < 2; rr++) {
            int row = sub * 2 + rr;
            const __nv_bfloat16* s = gsrc + (size_t)(gbase + row) * HH + k0;
            uint32_t dst = dbase + (uint32_t)(row * 80);
            cp_async16(dst,      s);
            cp_async16(dst + 16, reinterpret_cast<const char*>(s) + 16);
            cp_async16(dst + 32, reinterpret_cast<const char*>(s) + 32);
            cp_async16(dst + 48, reinterpret_cast<const char*>(s) + 48);
        }
    };

    // fragment offsets (relative to buffer base, before ks byte offset)
    const uint32_t a_off0 = (uint32_t)((wm * 32 +      (l & 15)) * 80 + ((l >> 4) << 4));
    const uint32_t a_off1 = (uint32_t)((wm * 32 + 16 + (l & 15)) * 80 + ((l >> 4) << 4));
    const uint32_t b_row  = (uint32_t)((l & 7) + ((l >> 4) & 1) * 8);
    const uint32_t b_koff = (uint32_t)(((l >> 3) & 1) << 4);

    float acc[2][8][4];
#pragma unroll
    for (int f = 0; f < 2; f++)
#pragma unroll
        for (int i = 0; i < 8; i++)
#pragma unroll
            for (int j = 0; j < 4; j++) acc[f][i][j] = 0.0f;

    issue(0, 0);
    cp_commit();

    const int T = HH / 32;   // 16
    int p = 0;
#pragma unroll 1
    for (int tk = 0; tk < T; tk++) {
        if (tk + 1 < T) {
            issue((tk + 1) * 32, p ^ 1);
            cp_commit();
            cp_wait1();
        } else {
            cp_wait0();
        }
        __syncthreads();

        uint32_t base = smbase + (uint32_t)(p * 40960);
#pragma unroll
        for (int ks = 0; ks < 2; ks++) {
            uint32_t ksb = (uint32_t)(ks * 32);   // 16 bf16 = 32 bytes
            uint32_t ah[2][4], al[2][4];
            ldsm4(ah[0], base + a_off0 + ksb);
            ldsm4(ah[1], base + a_off1 + ksb);
            ldsm4(al[0], base + 10240 + a_off0 + ksb);
            ldsm4(al[1], base + 10240 + a_off1 + ksb);
#pragma unroll
            for (int q = 0; q < 4; q++) {
                uint32_t boff = (uint32_t)((wn * 64 + q * 16 + b_row) * 80) + b_koff + ksb;
                uint32_t bh[4], bl[4];
                ldsm4(bh, base + 20480 + boff);
                ldsm4(bl, base + 30720 + boff);
#pragma unroll
                for (int f = 0; f < 2; f++) {
#pragma unroll
                    for (int h = 0; h < 2; h++) {
                        float* a = acc[f][2 * q + h];
                        mma_bf16(a, ah[f], bh[2 * h], bh[2 * h + 1]);
                        mma_bf16(a, ah[f], bl[2 * h], bl[2 * h + 1]);
                        mma_bf16(a, al[f], bh[2 * h], bh[2 * h + 1]);
                    }
                }
            }
        }
        __syncthreads();
        p ^= 1;
    }

    // epilogue
    const int g  = l >> 2;
    const int tt = l & 3;
#pragma unroll
    for (int f = 0; f < 2; f++) {
        int m0 = bm + wm * 32 + f * 16 + g;
#pragma unroll
        for (int nb = 0; nb < 8; nb++) {
            int n = bn + wn * 64 + nb * 8 + tt * 2;
            float2 bia = *reinterpret_cast<const float2*>(g_BMS + n);
            float2 v0 = make_float2(acc[f][nb][0] + bia.x, acc[f][nb][1] + bia.y);
            float2 v1 = make_float2(acc[f][nb][2] + bia.x, acc[f][nb][3] + bia.y);
            *reinterpret_cast<float2*>(g_MS + (size_t)m0 * NMS + n)       = v0;
            *reinterpret_cast<float2*>(g_MS + (size_t)(m0 + 8) * NMS + n) = v1;
        }
    }
}

// ---------------- fused tail ----------------
__global__ void fused_tail(const float* __restrict__ x, const float* __restrict__ mask,
                           float* __restrict__ out,
                           uint32_t kc0, uint32_t kc1, uint32_t kn0, uint32_t kn1)
{
    int t = blockIdx.x * blockDim.x + threadIdx.x;
    if (t >= BB * DD) return;
    int b = t >> 8;
    int d = t & (DD - 1);

    const float* lrow = g_LG + (size_t)b * NLG + d * 10;
    const float* mrow = g_MS + (size_t)b * NMS + d * 20;
    float lg[KK], mu[KK], sc[KK];
#pragma unroll
    for (int j = 0; j < KK; j++) lg[j] = lrow[j];
#pragma unroll
    for (int j = 0; j < KK; j++) mu[j] = mrow[j];
#pragma unroll
    for (int j = 0; j < KK; j++) {
        float v = mrow[10 + j];
        sc[j] = fmaxf(v, 0.0f) + log1pf(expf(-fabsf(v))) + 0.001f;
    }
    float q  = 1.0f - mask[t];
    float xu = x[t] * q;

    float mx = lg[0];
#pragma unroll
    for (int j = 1; j < KK; j++) mx = fmaxf(mx, lg[j]);
    float se = 0.0f;
#pragma unroll
    for (int j = 0; j < KK; j++) se += expf(lg[j] - mx);
    float lse = logf(se);

    float term[KK];
    float m2 = -1e30f;
#pragma unroll
    for (int j = 0; j < KK; j++) {
        float z   = (xu - mu[j]) / sc[j];
        float cll = -0.5f * z * z - logf(sc[j]) - 0.9189385332046727f;
        term[j] = (lg[j] - mx - lse) + cll;
        m2 = fmaxf(m2, term[j]);
    }
    float s2 = 0.0f;
#pragma unroll
    for (int j = 0; j < KK; j++) s2 += expf(term[j] - m2);
    out[t] = (m2 + logf(s2)) * q;

    float pm = 0.0f;
#pragma unroll
    for (int j = 0; j < KK; j++) pm += (expf(lg[j] - mx) / se) * mu[j];
    out[BB * DD + SS * BB * DD + t] = pm * q;

    float* smp = out + BB * DD;

#pragma unroll 1
    for (int s = 0; s < SS; s++) {
        uint32_t idx_e = (uint32_t)(s * BB + b) * DD + (uint32_t)d;
        uint32_t base  = idx_e * KK;
        float best = -1e30f;
        int a = 0;
#pragma unroll
        for (int j = 0; j < KK; j++) {
            uint32_t bits = tf_bits(kc0, kc1, base + j);
            float v = lg[j] + gumbel_from_bits(bits);
            if (v > best) { best = v; a = j; }
        }
        float mua = 0.f, sca = 0.f;
#pragma unroll
        for (int j = 0; j < KK; j++) {
            if (a == j) { mua = mu[j]; sca = sc[j]; }
        }
        uint32_t ebits = tf_bits(kn0, kn1, idx_e);
        const float LO = -0.99999994f;
        float u = fmaxf(LO, fmaf(bits_to_unit(ebits), 2.0f, LO));
        float eps = 1.41421356237309515f * erfinv_xla(u);
        smp[(b * SS + s) * DD + d] = (mua + sca * eps) * q;
    }
}

// ---------------- launch ----------------
extern "C" void kernel_launch(void* const* d_in, const int* in_sizes, int n_in,
                              void* d_out, int out_size)
{
    const float* x     = (const float*)d_in[0];
    const float* mask  = (const float*)d_in[1];
    const float* W_in  = (const float*)d_in[2];
    const float* b_in  = (const float*)d_in[3];
    const float* W1    = (const float*)d_in[4];
    const float* b1    = (const float*)d_in[5];
    const float* W2    = (const float*)d_in[6];
    const float* b2    = (const float*)d_in[7];
    const float* W_fin = (const float*)d_in[8];
    const float* b_fin = (const float*)d_in[9];
    float* out = (float*)d_out;

    float *dH, *dT, *dWLG, *dBLG, *dLG;
    cudaGetSymbolAddress((void**)&dH,   g_H);
    cudaGetSymbolAddress((void**)&dT,   g_T);
    cudaGetSymbolAddress((void**)&dWLG, g_WLG);
    cudaGetSymbolAddress((void**)&dBLG, g_BLG);
    cudaGetSymbolAddress((void**)&dLG,  g_LG);

    uint32_t kc0, kc1, kn0, kn1;
    threefry2x32(0u, 1234u, 0u, 0u, kc0, kc1);   // keys[0] -> categorical
    threefry2x32(0u, 1234u, 0u, 1u, kn0, kn1);   // keys[1] -> normal

    const int SMEM_MMA = 2 * 40960;              // 81920 B
    cudaFuncSetAttribute(musc_mma2,
                         cudaFuncAttributeMaxDynamicSharedMemorySize, SMEM_MMA);

    gather_lg<<<(HH * NLG + NLG + 255) / 256, 256>>>(W_fin, b_fin);
    gather_ms_t<<<dim3(NMS / 32, HH / 32), 256>>>(W_fin);
    gather_bms<<<(NMS + 255) / 256, 256>>>(b_fin);

    dim3 blk(128);
    dim3 g1(HH / 128, BB / 64);                  // 4 x 64 = 256 CTAs
    // h = concat(x*mask, mask) @ W_in + b_in
    sgemm_f32x2<false, false, true><<<g1, blk>>>(x, mask, W_in, b_in, dH, HH, 2 * DD);
    for (int l = 0; l < LL; l++) {
        sgemm_f32x2<true, false, false><<<g1, blk>>>(dH, nullptr, W1 + (size_t)l * HH * HH, b1 + l * HH, dT, HH, HH);
        sgemm_f32x2<true, true,  false><<<g1, blk>>>(dT, nullptr, W2 + (size_t)l * HH * HH, b2 + l * HH, dH, HH, HH);
    }

    // split H into bf16 hi/lo
    h2bf<<<(BB * HH + 255) / 256, 256>>>();

    // logits: exact fp32 GEMM (argmax-safe; DO NOT change numerics)
    dim3 g2(NLG / 128, BB / 64);                 // 20 x 64 = 1280 CTAs
    sgemm_f32x2<false, false, false><<<g2, blk>>>(dH, nullptr, dWLG, dBLG, dLG, NLG, HH);

    // means/scales: bf16-split tensor-core GEMM v2
    dim3 g3(NMS / 128, BB / 128);                // 40 x 32 = 1280 CTAs
    musc_mma2<<<g3, 256, SMEM_MMA>>>();

    fused_tail<<<(BB * DD + 255) / 256, 256>>>(x, mask, out, kc0, kc1, kn0, kn1);
}